// round 5
// baseline (speedup 1.0000x reference)
#include <cuda_runtime.h>
#include <cuda_fp16.h>
#include <cstdint>

// Problem constants
#define B_    64
#define S_    512
#define T_    32
#define H2_   1024
#define ATT_  512
#define WSTR_ 2048

// GEMM tiling (fp16 mma.m16n8k16, fp32 accum)
#define BM 128
#define BN 128
#define BK 32
#define NIT (H2_ / BK)          // 32
#define RPW 20                  // uint32 per padded smem row (80 B)
#define ROWB 80
#define A_BYTES (BM * ROWB)     // 10240
#define B_BYTES (BN * ROWB)     // 10240
#define STAGE (A_BYTES + B_BYTES)          // 20480
#define GEMM_SMEM (2 * STAGE)              // 40960

// Scratch (device globals)
__device__ __half g_h16[(size_t)B_ * S_ * H2_];   // 64 MB fp16 copy of h
__device__ __half g_w16[ATT_ * H2_];              // fp16 copy of w1_w[:, :1024]
__device__ float  g_ht_mean[B_ * H2_];
__device__ float  g_c[B_ * ATT_];
__device__ float  g_beta_part[4][B_ * S_];
__device__ float  g_alpha[B_ * S_];

// ---------------------------------------------------------------------------
__device__ __forceinline__ void cp16(uint32_t smem_dst, const void* gsrc) {
    asm volatile("cp.async.cg.shared.global [%0], [%1], 16;\n"
                 :: "r"(smem_dst), "l"(gsrc));
}
#define CP_COMMIT asm volatile("cp.async.commit_group;\n" ::: "memory")
#define CP_WAIT0  asm volatile("cp.async.wait_group 0;\n" ::: "memory")

__device__ __forceinline__ uint32_t smem_u32(const void* p) {
    uint32_t a;
    asm("{ .reg .u64 t; cvta.to.shared.u64 t, %1; cvt.u32.u64 %0, t; }"
        : "=r"(a) : "l"(p));
    return a;
}

__device__ __forceinline__ void mma_f16(float* d, const uint32_t* a,
                                        const uint32_t* b) {
    asm volatile(
        "mma.sync.aligned.m16n8k16.row.col.f32.f16.f16.f32 "
        "{%0,%1,%2,%3}, {%4,%5,%6,%7}, {%8,%9}, {%0,%1,%2,%3};\n"
        : "+f"(d[0]), "+f"(d[1]), "+f"(d[2]), "+f"(d[3])
        : "r"(a[0]), "r"(a[1]), "r"(a[2]), "r"(a[3]), "r"(b[0]), "r"(b[1]));
}

__device__ __forceinline__ float tanh_hw(float x) {
    float t;
    asm("tanh.approx.f32 %0, %1;" : "=f"(t) : "f"(x));
    return t;
}

// ---------------------------------------------------------------------------
// Converters: fp32 -> fp16
// ---------------------------------------------------------------------------
__global__ void k_cvt_h(const float* __restrict__ h) {
    size_t i = ((size_t)blockIdx.x * 256 + threadIdx.x) * 8;
    float4 f0 = *reinterpret_cast<const float4*>(h + i);
    float4 f1 = *reinterpret_cast<const float4*>(h + i + 4);
    __half2 a = __floats2half2_rn(f0.x, f0.y);
    __half2 b = __floats2half2_rn(f0.z, f0.w);
    __half2 c = __floats2half2_rn(f1.x, f1.y);
    __half2 d = __floats2half2_rn(f1.z, f1.w);
    uint4 v;
    v.x = *reinterpret_cast<uint32_t*>(&a);
    v.y = *reinterpret_cast<uint32_t*>(&b);
    v.z = *reinterpret_cast<uint32_t*>(&c);
    v.w = *reinterpret_cast<uint32_t*>(&d);
    *reinterpret_cast<uint4*>(&g_h16[i]) = v;
}

__global__ void k_cvt_w(const float* __restrict__ w1_w) {
    size_t i = ((size_t)blockIdx.x * 256 + threadIdx.x) * 8;
    int row = (int)(i >> 10);
    int col = (int)(i & 1023);
    const float* src = w1_w + (size_t)row * WSTR_ + col;
    float4 f0 = *reinterpret_cast<const float4*>(src);
    float4 f1 = *reinterpret_cast<const float4*>(src + 4);
    __half2 a = __floats2half2_rn(f0.x, f0.y);
    __half2 b = __floats2half2_rn(f0.z, f0.w);
    __half2 c = __floats2half2_rn(f1.x, f1.y);
    __half2 d = __floats2half2_rn(f1.z, f1.w);
    uint4 v;
    v.x = *reinterpret_cast<uint32_t*>(&a);
    v.y = *reinterpret_cast<uint32_t*>(&b);
    v.z = *reinterpret_cast<uint32_t*>(&c);
    v.w = *reinterpret_cast<uint32_t*>(&d);
    *reinterpret_cast<uint4*>(&g_w16[i]) = v;
}

// ---------------------------------------------------------------------------
__global__ void k_ht_mean(const float* __restrict__ ht) {
    int idx = blockIdx.x * 256 + threadIdx.x;
    int b = idx >> 10;
    const float* p = ht + (size_t)b * T_ * H2_ + (idx & (H2_ - 1));
    float s = 0.f;
#pragma unroll
    for (int t = 0; t < T_; ++t) s += p[(size_t)t * H2_];
    g_ht_mean[idx] = s * (1.0f / T_);
}

// ---------------------------------------------------------------------------
// c[b,a] = dot(ht_mean[b], w1_w[a, 1024:]) + bias[a]
// grid 64 blocks: block owns 8 a-rows (cached in smem), loops all 64 b.
// ---------------------------------------------------------------------------
__global__ __launch_bounds__(256) void k_c(const float* __restrict__ w1_w,
                                           const float* __restrict__ w1_b) {
    __shared__ float sw[8][H2_];   // 32 KB
    const int a0 = blockIdx.x * 8;
    const int tid = threadIdx.x;
    for (int i = tid; i < 8 * 256; i += 256) {       // float4 chunks
        int row = i >> 8, c4 = i & 255;
        reinterpret_cast<float4*>(sw[row])[c4] =
            *reinterpret_cast<const float4*>(
                w1_w + (size_t)(a0 + row) * WSTR_ + H2_ + c4 * 4);
    }
    __syncthreads();
    const int wid = tid >> 5, lane = tid & 31;
    const float bias = w1_b[a0 + wid];
    const float4* swv = reinterpret_cast<const float4*>(sw[wid]);
    for (int b = 0; b < B_; ++b) {
        const float4* hm =
            reinterpret_cast<const float4*>(g_ht_mean + b * H2_);
        float s = 0.f;
#pragma unroll
        for (int q = 0; q < 8; ++q) {
            float4 hv = hm[lane + q * 32];
            float4 wv = swv[lane + q * 32];
            s += hv.x * wv.x + hv.y * wv.y + hv.z * wv.z + hv.w * wv.w;
        }
#pragma unroll
        for (int off = 16; off; off >>= 1)
            s += __shfl_down_sync(0xffffffffu, s, off);
        if (lane == 0) g_c[b * ATT_ + a0 + wid] = s + bias;
    }
}

// ---------------------------------------------------------------------------
// Main fused GEMM (fp16 HMMA, fp32 accum), 128x128 tile, 256 threads,
// 2 CTAs/SM. beta_part = sum_n u[n]*tanh(z + c[b,n])
// ---------------------------------------------------------------------------
__global__ __launch_bounds__(256, 2) void k_gemm_beta(
    const float* __restrict__ u_w)
{
    extern __shared__ char smem[];
    const uint32_t sb = smem_u32(smem);

    const int tid = threadIdx.x;
    const int lane = tid & 31;
    const int wid = tid >> 5;
    const int warp_m = wid >> 1;      // 0..3, 32 rows
    const int warp_n = wid & 1;       // 0..1, 64 cols
    const int r = lane >> 2;          // 0..7
    const int t = lane & 3;           // 0..3

    const int n0 = blockIdx.x * BN;
    const int m0 = blockIdx.y * BM;
    const int b_idx = m0 >> 9;

    float acc[2][8][4];
#pragma unroll
    for (int i = 0; i < 2; ++i)
#pragma unroll
        for (int j = 0; j < 8; ++j)
#pragma unroll
            for (int q = 0; q < 4; ++q) acc[i][j][q] = 0.f;

    auto load_stage = [&](int it) {
        const uint32_t base = sb + (uint32_t)(it & 1) * STAGE;
        const int kb = it * BK;
#pragma unroll
        for (int s = 0; s < 2; ++s) {          // A: 512 16B chunks
            int id = tid + s * 256;
            int row = id >> 2, q = id & 3;
            cp16(base + (uint32_t)(row * ROWB + q * 16),
                 g_h16 + (size_t)(m0 + row) * H2_ + kb + q * 8);
        }
#pragma unroll
        for (int s = 0; s < 2; ++s) {          // B: 512 chunks
            int id = tid + s * 256;
            int row = id >> 2, q = id & 3;
            cp16(base + A_BYTES + (uint32_t)(row * ROWB + q * 16),
                 g_w16 + (size_t)(n0 + row) * H2_ + kb + q * 8);
        }
        CP_COMMIT;
    };

    load_stage(0);

    for (int it = 0; it < NIT; ++it) {
        CP_WAIT0;
        __syncthreads();
        if (it + 1 < NIT) load_stage(it + 1);

        const uint32_t* pA = reinterpret_cast<const uint32_t*>(
            smem + (it & 1) * STAGE);
        const uint32_t* pB = pA + A_BYTES / 4;

#pragma unroll
        for (int ks = 0; ks < 2; ++ks) {
            uint32_t af[2][4], bf[8][2];
#pragma unroll
            for (int mf = 0; mf < 2; ++mf) {
                const uint32_t* p =
                    pA + (warp_m * 32 + mf * 16 + r) * RPW + ks * 8 + t;
                af[mf][0] = p[0];
                af[mf][1] = p[8 * RPW];
                af[mf][2] = p[4];
                af[mf][3] = p[8 * RPW + 4];
            }
#pragma unroll
            for (int nf = 0; nf < 8; ++nf) {
                const uint32_t* p =
                    pB + (warp_n * 64 + nf * 8 + r) * RPW + ks * 8 + t;
                bf[nf][0] = p[0];
                bf[nf][1] = p[4];
            }
#pragma unroll
            for (int mf = 0; mf < 2; ++mf)
#pragma unroll
                for (int nf = 0; nf < 8; ++nf)
                    mma_f16(acc[mf][nf], af[mf], bf[nf]);
        }
    }

    // ---- fused epilogue ----
    float uv[8][2], cv[8][2];
#pragma unroll
    for (int nf = 0; nf < 8; ++nf)
#pragma unroll
        for (int j = 0; j < 2; ++j) {
            int n = n0 + warp_n * 64 + nf * 8 + t * 2 + j;
            uv[nf][j] = u_w[n];
            cv[nf][j] = g_c[b_idx * ATT_ + n];
        }

    float part[2][2];
#pragma unroll
    for (int mf = 0; mf < 2; ++mf)
#pragma unroll
        for (int half = 0; half < 2; ++half) {
            float p = 0.f;
#pragma unroll
            for (int nf = 0; nf < 8; ++nf)
#pragma unroll
                for (int j = 0; j < 2; ++j) {
                    float z = acc[mf][nf][half * 2 + j] + cv[nf][j];
                    p += uv[nf][j] * tanh_hw(z);
                }
            part[mf][half] = p;
        }

#pragma unroll
    for (int mf = 0; mf < 2; ++mf)
#pragma unroll
        for (int half = 0; half < 2; ++half) {
            float p = part[mf][half];
            p += __shfl_xor_sync(0xffffffffu, p, 1);
            p += __shfl_xor_sync(0xffffffffu, p, 2);
            part[mf][half] = p;
        }

    __syncthreads();
    float* red = reinterpret_cast<float*>(smem);   // [128][2]
    if (t == 0) {
#pragma unroll
        for (int mf = 0; mf < 2; ++mf)
#pragma unroll
            for (int half = 0; half < 2; ++half) {
                int row = warp_m * 32 + mf * 16 + half * 8 + r;
                red[row * 2 + warp_n] = part[mf][half];
            }
    }
    __syncthreads();
    if (tid < BM)
        g_beta_part[blockIdx.x][m0 + tid] = red[tid * 2] + red[tid * 2 + 1];
}

// ---------------------------------------------------------------------------
__global__ void k_softmax(const int* __restrict__ h_mask) {
    int b = blockIdx.x;
    int s = threadIdx.x;
    int idx = b * S_ + s;
    float beta = g_beta_part[0][idx] + g_beta_part[1][idx] +
                 g_beta_part[2][idx] + g_beta_part[3][idx];
    bool valid = h_mask[idx] != 0;
    beta = valid ? beta : -1e20f;

    __shared__ float sm[512];
    sm[s] = beta;
    __syncthreads();
#pragma unroll
    for (int off = 256; off; off >>= 1) {
        if (s < off) sm[s] = fmaxf(sm[s], sm[s + off]);
        __syncthreads();
    }
    float mx = sm[0];
    __syncthreads();
    float e = __expf(beta - mx);
    sm[s] = e;
    __syncthreads();
#pragma unroll
    for (int off = 256; off; off >>= 1) {
        if (s < off) sm[s] += sm[s + off];
        __syncthreads();
    }
    g_alpha[idx] = e * (1.0f / sm[0]);
}

// ---------------------------------------------------------------------------
// out[b,d] = sum_s alpha[b,s] * h16[b,s,d]   (fp16 h copy, fp32 accumulate)
// 1 block per b, 256 threads: tid<128 does s in [0,256), else [256,512).
// Each thread owns 8 consecutive d (one uint4 of halves per s).
// ---------------------------------------------------------------------------
__global__ __launch_bounds__(256) void k_out(float* __restrict__ out) {
    const int b = blockIdx.x;
    const int tid = threadIdx.x;
    __shared__ float sal[S_];
    __shared__ float sred[128 * 8];
    for (int i = tid; i < S_; i += 256) sal[i] = g_alpha[b * S_ + i];
    __syncthreads();

    const int hhalf = tid >> 7;        // 0/1
    const int dt = tid & 127;
    const int d0 = dt * 8;
    float acc[8];
#pragma unroll
    for (int k = 0; k < 8; ++k) acc[k] = 0.f;

    const __half* hb = g_h16 + ((size_t)b * S_ + hhalf * 256) * H2_ + d0;
    const float* al = sal + hhalf * 256;
#pragma unroll 4
    for (int s = 0; s < 256; ++s) {
        uint4 v = *reinterpret_cast<const uint4*>(hb + (size_t)s * H2_);
        float a = al[s];
        float2 p0 = __half22float2(*reinterpret_cast<__half2*>(&v.x));
        float2 p1 = __half22float2(*reinterpret_cast<__half2*>(&v.y));
        float2 p2 = __half22float2(*reinterpret_cast<__half2*>(&v.z));
        float2 p3 = __half22float2(*reinterpret_cast<__half2*>(&v.w));
        acc[0] += a * p0.x; acc[1] += a * p0.y;
        acc[2] += a * p1.x; acc[3] += a * p1.y;
        acc[4] += a * p2.x; acc[5] += a * p2.y;
        acc[6] += a * p3.x; acc[7] += a * p3.y;
    }
    if (hhalf) {
#pragma unroll
        for (int k = 0; k < 8; ++k) sred[dt * 8 + k] = acc[k];
    }
    __syncthreads();
    if (!hhalf) {
#pragma unroll
        for (int k = 0; k < 8; ++k)
            out[b * H2_ + d0 + k] = acc[k] + sred[dt * 8 + k];
    }
}

// ---------------------------------------------------------------------------
extern "C" void kernel_launch(void* const* d_in, const int* in_sizes, int n_in,
                              void* d_out, int out_size) {
    const float* h      = (const float*)d_in[0];
    const int*   h_mask = (const int*)  d_in[1];
    const float* ht     = (const float*)d_in[2];
    const float* w1_w   = (const float*)d_in[3];
    const float* w1_b   = (const float*)d_in[4];
    const float* u_w    = (const float*)d_in[5];
    float* out = (float*)d_out;

    cudaFuncSetAttribute(k_gemm_beta,
                         cudaFuncAttributeMaxDynamicSharedMemorySize,
                         GEMM_SMEM);

    k_cvt_h<<<(B_ * S_ * H2_) / (256 * 8), 256>>>(h);
    k_cvt_w<<<(ATT_ * H2_) / (256 * 8), 256>>>(w1_w);
    k_ht_mean<<<(B_ * H2_) / 256, 256>>>(ht);
    k_c<<<ATT_ / 8, 256>>>(w1_w, w1_b);
    k_gemm_beta<<<dim3(ATT_ / BN, (B_ * S_) / BM), 256, GEMM_SMEM>>>(u_w);
    k_softmax<<<B_, S_>>>(h_mask);
    k_out<<<B_, 256>>>(out);
}

// round 6
// speedup vs baseline: 1.1336x; 1.1336x over previous
#include <cuda_runtime.h>
#include <cuda_fp16.h>
#include <cstdint>

// Problem constants
#define B_    64
#define S_    512
#define T_    32
#define H2_   1024
#define ATT_  512
#define WSTR_ 2048

// GEMM tiling (fp16 mma.m16n8k16, fp32 accum)
#define BM 128
#define BN 128
#define BK 32
#define NIT (H2_ / BK)          // 32
#define RPW 20                  // uint32 per padded smem row (80 B)
#define ROWB 80
#define A_BYTES (BM * ROWB)     // 10240
#define B_BYTES (BN * ROWB)     // 10240
#define STAGE (A_BYTES + B_BYTES)          // 20480
#define GEMM_SMEM (2 * STAGE)              // 40960

// Scratch (device globals)
__device__ __half g_w16[ATT_ * H2_];              // fp16 copy of w1_w[:, :1024]
__device__ float  g_ht_mean[B_ * H2_];
__device__ float  g_c[B_ * ATT_];
__device__ float  g_beta_part[4][B_ * S_];

// ---------------------------------------------------------------------------
__device__ __forceinline__ void cp16(uint32_t smem_dst, const void* gsrc) {
    asm volatile("cp.async.cg.shared.global [%0], [%1], 16;\n"
                 :: "r"(smem_dst), "l"(gsrc));
}
#define CP_COMMIT asm volatile("cp.async.commit_group;\n" ::: "memory")
#define CP_WAIT0  asm volatile("cp.async.wait_group 0;\n" ::: "memory")

__device__ __forceinline__ uint32_t smem_u32(const void* p) {
    uint32_t a;
    asm("{ .reg .u64 t; cvta.to.shared.u64 t, %1; cvt.u32.u64 %0, t; }"
        : "=r"(a) : "l"(p));
    return a;
}

__device__ __forceinline__ void mma_f16(float* d, const uint32_t* a,
                                        const uint32_t* b) {
    asm volatile(
        "mma.sync.aligned.m16n8k16.row.col.f32.f16.f16.f32 "
        "{%0,%1,%2,%3}, {%4,%5,%6,%7}, {%8,%9}, {%0,%1,%2,%3};\n"
        : "+f"(d[0]), "+f"(d[1]), "+f"(d[2]), "+f"(d[3])
        : "r"(a[0]), "r"(a[1]), "r"(a[2]), "r"(a[3]), "r"(b[0]), "r"(b[1]));
}

__device__ __forceinline__ float tanh_hw(float x) {
    float t;
    asm("tanh.approx.f32 %0, %1;" : "=f"(t) : "f"(x));
    return t;
}

// ---------------------------------------------------------------------------
__global__ void k_cvt_w(const float* __restrict__ w1_w) {
    size_t i = ((size_t)blockIdx.x * 256 + threadIdx.x) * 8;
    int row = (int)(i >> 10);
    int col = (int)(i & 1023);
    const float* src = w1_w + (size_t)row * WSTR_ + col;
    float4 f0 = *reinterpret_cast<const float4*>(src);
    float4 f1 = *reinterpret_cast<const float4*>(src + 4);
    __half2 a = __floats2half2_rn(f0.x, f0.y);
    __half2 b = __floats2half2_rn(f0.z, f0.w);
    __half2 c = __floats2half2_rn(f1.x, f1.y);
    __half2 d = __floats2half2_rn(f1.z, f1.w);
    uint4 v;
    v.x = *reinterpret_cast<uint32_t*>(&a);
    v.y = *reinterpret_cast<uint32_t*>(&b);
    v.z = *reinterpret_cast<uint32_t*>(&c);
    v.w = *reinterpret_cast<uint32_t*>(&d);
    *reinterpret_cast<uint4*>(&g_w16[i]) = v;
}

__global__ void k_ht_mean(const float* __restrict__ ht) {
    int idx = blockIdx.x * 256 + threadIdx.x;
    int b = idx >> 10;
    const float* p = ht + (size_t)b * T_ * H2_ + (idx & (H2_ - 1));
    float s = 0.f;
#pragma unroll
    for (int t = 0; t < T_; ++t) s += p[(size_t)t * H2_];
    g_ht_mean[idx] = s * (1.0f / T_);
}

// ---------------------------------------------------------------------------
// c[b,a] = dot(ht_mean[b], w1_w[a,1024:]) + bias[a]
// grid (64 a-chunks, 8 b-chunks); block caches 8 w-rows in smem,
// warp w handles a-row a0+w for 8 batches.
// ---------------------------------------------------------------------------
__global__ __launch_bounds__(256) void k_c(const float* __restrict__ w1_w,
                                           const float* __restrict__ w1_b) {
    __shared__ float sw[8][H2_];   // 32 KB
    const int a0 = blockIdx.x * 8;
    const int b0 = blockIdx.y * 8;
    const int tid = threadIdx.x;
    for (int i = tid; i < 8 * 256; i += 256) {
        int row = i >> 8, c4 = i & 255;
        reinterpret_cast<float4*>(sw[row])[c4] =
            *reinterpret_cast<const float4*>(
                w1_w + (size_t)(a0 + row) * WSTR_ + H2_ + c4 * 4);
    }
    __syncthreads();
    const int wid = tid >> 5, lane = tid & 31;
    const float bias = w1_b[a0 + wid];
    const float4* swv = reinterpret_cast<const float4*>(sw[wid]);
#pragma unroll
    for (int bi = 0; bi < 8; ++bi) {
        int b = b0 + bi;
        const float4* hm =
            reinterpret_cast<const float4*>(g_ht_mean + b * H2_);
        float s = 0.f;
#pragma unroll
        for (int q = 0; q < 8; ++q) {
            float4 hv = hm[lane + q * 32];
            float4 wv = swv[lane + q * 32];
            s += hv.x * wv.x + hv.y * wv.y + hv.z * wv.z + hv.w * wv.w;
        }
#pragma unroll
        for (int off = 16; off; off >>= 1)
            s += __shfl_down_sync(0xffffffffu, s, off);
        if (lane == 0) g_c[b * ATT_ + a0 + wid] = s + bias;
    }
}

// ---------------------------------------------------------------------------
// Main fused GEMM (fp16 HMMA, fp32 accum), 128x128 tile, 256 threads,
// 2 CTAs/SM. A read as fp32 from h (LDG -> cvt -> STS fp16).
// beta_part = sum_n u[n]*tanh(z + c[b,n])
// ---------------------------------------------------------------------------
__global__ __launch_bounds__(256, 2) void k_gemm_beta(
    const float* __restrict__ h,
    const float* __restrict__ u_w)
{
    extern __shared__ char smem[];
    const uint32_t sb = smem_u32(smem);

    const int tid = threadIdx.x;
    const int lane = tid & 31;
    const int wid = tid >> 5;
    const int warp_m = wid >> 1;      // 0..3, 32 rows
    const int warp_n = wid & 1;       // 0..1, 64 cols
    const int r = lane >> 2;          // 0..7
    const int t = lane & 3;           // 0..3

    const int n0 = blockIdx.x * BN;
    const int m0 = blockIdx.y * BM;
    const int b_idx = m0 >> 9;

    // A staging: thread owns row tid>>1, 16 consecutive k at (tid&1)*16
    const int arow = tid >> 1;
    const int acol = (tid & 1) * 16;
    const float* aptr = h + (size_t)(m0 + arow) * H2_ + acol;
    const uint32_t asmem = (uint32_t)(arow * ROWB + acol * 2);

    float acc[2][8][4];
#pragma unroll
    for (int i = 0; i < 2; ++i)
#pragma unroll
        for (int j = 0; j < 8; ++j)
#pragma unroll
            for (int q = 0; q < 4; ++q) acc[i][j][q] = 0.f;

    float4 areg[4];
    auto ldg_a = [&](int it) {
        const float* p = aptr + it * BK;
#pragma unroll
        for (int q = 0; q < 4; ++q)
            areg[q] = *reinterpret_cast<const float4*>(p + q * 4);
    };
    auto sts_a = [&](int it) {
        uint32_t u[8];
#pragma unroll
        for (int q = 0; q < 4; ++q) {
            __half2 lo = __floats2half2_rn(areg[q].x, areg[q].y);
            __half2 hi = __floats2half2_rn(areg[q].z, areg[q].w);
            u[q * 2]     = *reinterpret_cast<uint32_t*>(&lo);
            u[q * 2 + 1] = *reinterpret_cast<uint32_t*>(&hi);
        }
        uint32_t dst = sb + (uint32_t)(it & 1) * STAGE + asmem;
        asm volatile("st.shared.v4.b32 [%0], {%1,%2,%3,%4};"
                     :: "r"(dst), "r"(u[0]), "r"(u[1]), "r"(u[2]), "r"(u[3]));
        asm volatile("st.shared.v4.b32 [%0], {%1,%2,%3,%4};"
                     :: "r"(dst + 16), "r"(u[4]), "r"(u[5]), "r"(u[6]), "r"(u[7]));
    };
    auto ld_b = [&](int it) {
        const uint32_t base = sb + (uint32_t)(it & 1) * STAGE + A_BYTES;
        const int kb = it * BK;
#pragma unroll
        for (int s = 0; s < 2; ++s) {          // B: 512 16B chunks
            int id = tid + s * 256;
            int row = id >> 2, q = id & 3;
            cp16(base + (uint32_t)(row * ROWB + q * 16),
                 g_w16 + (size_t)(n0 + row) * H2_ + kb + q * 8);
        }
        CP_COMMIT;
    };

    ldg_a(0);
    ld_b(0);

    for (int it = 0; it < NIT; ++it) {
        CP_WAIT0;
        sts_a(it);
        __syncthreads();
        if (it + 1 < NIT) {
            ldg_a(it + 1);
            ld_b(it + 1);
        }

        const uint32_t* pA = reinterpret_cast<const uint32_t*>(
            smem + (it & 1) * STAGE);
        const uint32_t* pB = pA + A_BYTES / 4;

#pragma unroll
        for (int ks = 0; ks < 2; ++ks) {
            uint32_t af[2][4], bf[8][2];
#pragma unroll
            for (int mf = 0; mf < 2; ++mf) {
                const uint32_t* p =
                    pA + (warp_m * 32 + mf * 16 + r) * RPW + ks * 8 + t;
                af[mf][0] = p[0];
                af[mf][1] = p[8 * RPW];
                af[mf][2] = p[4];
                af[mf][3] = p[8 * RPW + 4];
            }
#pragma unroll
            for (int nf = 0; nf < 8; ++nf) {
                const uint32_t* p =
                    pB + (warp_n * 64 + nf * 8 + r) * RPW + ks * 8 + t;
                bf[nf][0] = p[0];
                bf[nf][1] = p[4];
            }
#pragma unroll
            for (int mf = 0; mf < 2; ++mf)
#pragma unroll
                for (int nf = 0; nf < 8; ++nf)
                    mma_f16(acc[mf][nf], af[mf], bf[nf]);
        }
    }

    // ---- fused epilogue ----
    float uv[8][2], cv[8][2];
#pragma unroll
    for (int nf = 0; nf < 8; ++nf)
#pragma unroll
        for (int j = 0; j < 2; ++j) {
            int n = n0 + warp_n * 64 + nf * 8 + t * 2 + j;
            uv[nf][j] = u_w[n];
            cv[nf][j] = g_c[b_idx * ATT_ + n];
        }

    float part[2][2];
#pragma unroll
    for (int mf = 0; mf < 2; ++mf)
#pragma unroll
        for (int half = 0; half < 2; ++half) {
            float p = 0.f;
#pragma unroll
            for (int nf = 0; nf < 8; ++nf)
#pragma unroll
                for (int j = 0; j < 2; ++j) {
                    float z = acc[mf][nf][half * 2 + j] + cv[nf][j];
                    p += uv[nf][j] * tanh_hw(z);
                }
            part[mf][half] = p;
        }

#pragma unroll
    for (int mf = 0; mf < 2; ++mf)
#pragma unroll
        for (int half = 0; half < 2; ++half) {
            float p = part[mf][half];
            p += __shfl_xor_sync(0xffffffffu, p, 1);
            p += __shfl_xor_sync(0xffffffffu, p, 2);
            part[mf][half] = p;
        }

    __syncthreads();
    float* red = reinterpret_cast<float*>(smem);   // [128][2]
    if (t == 0) {
#pragma unroll
        for (int mf = 0; mf < 2; ++mf)
#pragma unroll
            for (int half = 0; half < 2; ++half) {
                int row = warp_m * 32 + mf * 16 + half * 8 + r;
                red[row * 2 + warp_n] = part[mf][half];
            }
    }
    __syncthreads();
    if (tid < BM)
        g_beta_part[blockIdx.x][m0 + tid] = red[tid * 2] + red[tid * 2 + 1];
}

// ---------------------------------------------------------------------------
// Fused softmax + weighted sum.
// grid (4 d-chunks, 64 b). Each block: softmax over S (redundant across the 4
// d-chunk blocks, trivial), then out[b, dchunk*256 + ...] = sum_s alpha*h.
// Threads: ds = tid&63 owns 4 consecutive d; ss = tid>>6 covers 128 s each.
// ---------------------------------------------------------------------------
__global__ __launch_bounds__(256) void k_out(const int* __restrict__ h_mask,
                                             const float* __restrict__ h,
                                             float* __restrict__ out) {
    const int b = blockIdx.y;
    const int d0 = blockIdx.x * 256;
    const int tid = threadIdx.x;
    const int ds = tid & 63;
    const int ss = tid >> 6;

    __shared__ float salpha[S_];
    __shared__ float tmp[256];
    __shared__ float red[3][256];

    // --- softmax (each thread handles s = tid and tid+256) ---
    float beta[2];
#pragma unroll
    for (int k = 0; k < 2; ++k) {
        int s = tid + k * 256;
        int idx = b * S_ + s;
        float v = g_beta_part[0][idx] + g_beta_part[1][idx] +
                  g_beta_part[2][idx] + g_beta_part[3][idx];
        beta[k] = (h_mask[idx] != 0) ? v : -1e20f;
    }
    tmp[tid] = fmaxf(beta[0], beta[1]);
    __syncthreads();
#pragma unroll
    for (int off = 128; off; off >>= 1) {
        if (tid < off) tmp[tid] = fmaxf(tmp[tid], tmp[tid + off]);
        __syncthreads();
    }
    const float mx = tmp[0];
    __syncthreads();
    float e0 = __expf(beta[0] - mx);
    float e1 = __expf(beta[1] - mx);
    salpha[tid] = e0;
    salpha[tid + 256] = e1;
    tmp[tid] = e0 + e1;
    __syncthreads();
#pragma unroll
    for (int off = 128; off; off >>= 1) {
        if (tid < off) tmp[tid] += tmp[tid + off];
        __syncthreads();
    }
    const float inv = 1.0f / tmp[0];
    __syncthreads();

    // --- weighted sum over this thread's s-slice ---
    float acc[4] = {0.f, 0.f, 0.f, 0.f};
    const float* hp = h + ((size_t)b * S_ + ss * 128) * H2_ + d0 + ds * 4;
    const float* al = salpha + ss * 128;
#pragma unroll 8
    for (int s = 0; s < 128; ++s) {
        float4 v = *reinterpret_cast<const float4*>(hp + (size_t)s * H2_);
        float a = al[s];
        acc[0] += a * v.x; acc[1] += a * v.y;
        acc[2] += a * v.z; acc[3] += a * v.w;
    }
    if (ss) {
#pragma unroll
        for (int k = 0; k < 4; ++k) red[ss - 1][ds * 4 + k] = acc[k];
    }
    __syncthreads();
    if (ss == 0) {
#pragma unroll
        for (int k = 0; k < 4; ++k) {
            float v = acc[k] + red[0][ds * 4 + k] + red[1][ds * 4 + k] +
                      red[2][ds * 4 + k];
            out[b * H2_ + d0 + ds * 4 + k] = v * inv;
        }
    }
}

// ---------------------------------------------------------------------------
extern "C" void kernel_launch(void* const* d_in, const int* in_sizes, int n_in,
                              void* d_out, int out_size) {
    const float* h      = (const float*)d_in[0];
    const int*   h_mask = (const int*)  d_in[1];
    const float* ht     = (const float*)d_in[2];
    const float* w1_w   = (const float*)d_in[3];
    const float* w1_b   = (const float*)d_in[4];
    const float* u_w    = (const float*)d_in[5];
    float* out = (float*)d_out;

    cudaFuncSetAttribute(k_gemm_beta,
                         cudaFuncAttributeMaxDynamicSharedMemorySize,
                         GEMM_SMEM);

    k_cvt_w<<<(ATT_ * H2_) / (256 * 8), 256>>>(w1_w);
    k_ht_mean<<<(B_ * H2_) / 256, 256>>>(ht);
    k_c<<<dim3(ATT_ / 8, B_ / 8), 256>>>(w1_w, w1_b);
    k_gemm_beta<<<dim3(ATT_ / BN, (B_ * S_) / BM), 256, GEMM_SMEM>>>(h, u_w);
    k_out<<<dim3(4, B_), 256>>>(h_mask, h, out);
}

// round 7
// speedup vs baseline: 1.3012x; 1.1478x over previous
#include <cuda_runtime.h>
#include <cuda_fp16.h>
#include <cstdint>

// Problem constants
#define B_    64
#define S_    512
#define T_    32
#define H2_   1024
#define ATT_  512
#define WSTR_ 2048

// GEMM tiling (fp16 mma.m16n8k16, fp32 accum)
#define BM 128
#define BN 128
#define BK 32
#define NIT (H2_ / BK)          // 32
#define RPW 20                  // uint32 per padded smem row (80 B)
#define ROWB 80
#define A_BYTES (BM * ROWB)     // 10240
#define B_BYTES (BN * ROWB)     // 10240
#define STAGE (A_BYTES + B_BYTES)          // 20480
#define GEMM_SMEM (2 * STAGE)              // 40960

// Scratch (device globals)
__device__ __half g_w16[ATT_ * H2_];              // fp16 copy of w1_w[:, :1024]
__device__ float  g_ht_mean[B_ * H2_];
__device__ float  g_c[B_ * ATT_];
__device__ float  g_beta_part[4][B_ * S_];

// ---------------------------------------------------------------------------
__device__ __forceinline__ void cp16(uint32_t smem_dst, const void* gsrc) {
    asm volatile("cp.async.cg.shared.global [%0], [%1], 16;\n"
                 :: "r"(smem_dst), "l"(gsrc));
}
#define CP_COMMIT asm volatile("cp.async.commit_group;\n" ::: "memory")
#define CP_WAIT0  asm volatile("cp.async.wait_group 0;\n" ::: "memory")

__device__ __forceinline__ uint32_t smem_u32(const void* p) {
    uint32_t a;
    asm("{ .reg .u64 t; cvta.to.shared.u64 t, %1; cvt.u32.u64 %0, t; }"
        : "=r"(a) : "l"(p));
    return a;
}

__device__ __forceinline__ void mma_f16(float* d, const uint32_t* a,
                                        const uint32_t* b) {
    asm volatile(
        "mma.sync.aligned.m16n8k16.row.col.f32.f16.f16.f32 "
        "{%0,%1,%2,%3}, {%4,%5,%6,%7}, {%8,%9}, {%0,%1,%2,%3};\n"
        : "+f"(d[0]), "+f"(d[1]), "+f"(d[2]), "+f"(d[3])
        : "r"(a[0]), "r"(a[1]), "r"(a[2]), "r"(a[3]), "r"(b[0]), "r"(b[1]));
}

__device__ __forceinline__ void ldsm_x4(uint32_t& r0, uint32_t& r1,
                                        uint32_t& r2, uint32_t& r3,
                                        uint32_t addr) {
    asm volatile(
        "ldmatrix.sync.aligned.m8n8.x4.shared.b16 {%0,%1,%2,%3}, [%4];"
        : "=r"(r0), "=r"(r1), "=r"(r2), "=r"(r3) : "r"(addr));
}

__device__ __forceinline__ float tanh_hw(float x) {
    float t;
    asm("tanh.approx.f32 %0, %1;" : "=f"(t) : "f"(x));
    return t;
}

// ---------------------------------------------------------------------------
__global__ void k_cvt_w(const float* __restrict__ w1_w) {
    size_t i = ((size_t)blockIdx.x * 256 + threadIdx.x) * 8;
    int row = (int)(i >> 10);
    int col = (int)(i & 1023);
    const float* src = w1_w + (size_t)row * WSTR_ + col;
    float4 f0 = *reinterpret_cast<const float4*>(src);
    float4 f1 = *reinterpret_cast<const float4*>(src + 4);
    __half2 a = __floats2half2_rn(f0.x, f0.y);
    __half2 b = __floats2half2_rn(f0.z, f0.w);
    __half2 c = __floats2half2_rn(f1.x, f1.y);
    __half2 d = __floats2half2_rn(f1.z, f1.w);
    uint4 v;
    v.x = *reinterpret_cast<uint32_t*>(&a);
    v.y = *reinterpret_cast<uint32_t*>(&b);
    v.z = *reinterpret_cast<uint32_t*>(&c);
    v.w = *reinterpret_cast<uint32_t*>(&d);
    *reinterpret_cast<uint4*>(&g_w16[i]) = v;
}

__global__ void k_ht_mean(const float* __restrict__ ht) {
    int idx = blockIdx.x * 256 + threadIdx.x;
    int b = idx >> 10;
    const float* p = ht + (size_t)b * T_ * H2_ + (idx & (H2_ - 1));
    float s = 0.f;
#pragma unroll
    for (int t = 0; t < T_; ++t) s += p[(size_t)t * H2_];
    g_ht_mean[idx] = s * (1.0f / T_);
}

// ---------------------------------------------------------------------------
// c[b,a] = dot(ht_mean[b], w1_w[a,1024:]) + bias[a]
// ---------------------------------------------------------------------------
__global__ __launch_bounds__(256) void k_c(const float* __restrict__ w1_w,
                                           const float* __restrict__ w1_b) {
    __shared__ float sw[8][H2_];   // 32 KB
    const int a0 = blockIdx.x * 8;
    const int b0 = blockIdx.y * 8;
    const int tid = threadIdx.x;
    for (int i = tid; i < 8 * 256; i += 256) {
        int row = i >> 8, c4 = i & 255;
        reinterpret_cast<float4*>(sw[row])[c4] =
            *reinterpret_cast<const float4*>(
                w1_w + (size_t)(a0 + row) * WSTR_ + H2_ + c4 * 4);
    }
    __syncthreads();
    const int wid = tid >> 5, lane = tid & 31;
    const float bias = w1_b[a0 + wid];
    const float4* swv = reinterpret_cast<const float4*>(sw[wid]);
#pragma unroll
    for (int bi = 0; bi < 8; ++bi) {
        int b = b0 + bi;
        const float4* hm =
            reinterpret_cast<const float4*>(g_ht_mean + b * H2_);
        float s = 0.f;
#pragma unroll
        for (int q = 0; q < 8; ++q) {
            float4 hv = hm[lane + q * 32];
            float4 wv = swv[lane + q * 32];
            s += hv.x * wv.x + hv.y * wv.y + hv.z * wv.z + hv.w * wv.w;
        }
#pragma unroll
        for (int off = 16; off; off >>= 1)
            s += __shfl_down_sync(0xffffffffu, s, off);
        if (lane == 0) g_c[b * ATT_ + a0 + wid] = s + bias;
    }
}

// ---------------------------------------------------------------------------
// Main fused GEMM (fp16 HMMA, fp32 accum), 128x128 tile, 256 threads,
// 2 CTAs/SM, ldmatrix fragment loads.
// ---------------------------------------------------------------------------
__global__ __launch_bounds__(256, 2) void k_gemm_beta(
    const float* __restrict__ h,
    const float* __restrict__ u_w)
{
    extern __shared__ char smem[];
    const uint32_t sb = smem_u32(smem);

    const int tid = threadIdx.x;
    const int lane = tid & 31;
    const int wid = tid >> 5;
    const int warp_m = wid >> 1;      // 0..3, 32 rows
    const int warp_n = wid & 1;       // 0..1, 64 cols
    const int r = lane >> 2;          // 0..7
    const int t = lane & 3;           // 0..3

    const int n0 = blockIdx.x * BN;
    const int m0 = blockIdx.y * BM;
    const int b_idx = m0 >> 9;

    // ldmatrix per-lane base offsets (bytes)
    const int lane7 = lane & 7;
    const int lg8 = (lane >> 3) & 1;
    const int lg16 = lane >> 4;
    const uint32_t a_off =
        (uint32_t)((warp_m * 32 + lg8 * 8 + lane7) * ROWB + lg16 * 16);
    const uint32_t b_off =
        (uint32_t)(A_BYTES + (warp_n * 64 + lg8 * 8 + lane7) * ROWB +
                   lg16 * 16);

    // A staging: thread owns row tid>>1, 16 consecutive k at (tid&1)*16
    const int arow = tid >> 1;
    const int acol = (tid & 1) * 16;
    const float* aptr = h + (size_t)(m0 + arow) * H2_ + acol;
    const uint32_t asmem = (uint32_t)(arow * ROWB + acol * 2);

    float acc[2][8][4];
#pragma unroll
    for (int i = 0; i < 2; ++i)
#pragma unroll
        for (int j = 0; j < 8; ++j)
#pragma unroll
            for (int q = 0; q < 4; ++q) acc[i][j][q] = 0.f;

    float4 areg[4];
    auto ldg_a = [&](int it) {
        const float* p = aptr + it * BK;
#pragma unroll
        for (int q = 0; q < 4; ++q)
            areg[q] = *reinterpret_cast<const float4*>(p + q * 4);
    };
    auto sts_a = [&](int it) {
        uint32_t u[8];
#pragma unroll
        for (int q = 0; q < 4; ++q) {
            __half2 lo = __floats2half2_rn(areg[q].x, areg[q].y);
            __half2 hi = __floats2half2_rn(areg[q].z, areg[q].w);
            u[q * 2]     = *reinterpret_cast<uint32_t*>(&lo);
            u[q * 2 + 1] = *reinterpret_cast<uint32_t*>(&hi);
        }
        uint32_t dst = sb + (uint32_t)(it & 1) * STAGE + asmem;
        asm volatile("st.shared.v4.b32 [%0], {%1,%2,%3,%4};"
                     :: "r"(dst), "r"(u[0]), "r"(u[1]), "r"(u[2]), "r"(u[3]));
        asm volatile("st.shared.v4.b32 [%0], {%1,%2,%3,%4};"
                     :: "r"(dst + 16), "r"(u[4]), "r"(u[5]), "r"(u[6]), "r"(u[7]));
    };
    auto ld_b = [&](int it) {
        const uint32_t base = sb + (uint32_t)(it & 1) * STAGE + A_BYTES;
        const int kb = it * BK;
#pragma unroll
        for (int s = 0; s < 2; ++s) {
            int id = tid + s * 256;
            int row = id >> 2, q = id & 3;
            cp16(base + (uint32_t)(row * ROWB + q * 16),
                 g_w16 + (size_t)(n0 + row) * H2_ + kb + q * 8);
        }
        CP_COMMIT;
    };

    ldg_a(0);
    ld_b(0);

    for (int it = 0; it < NIT; ++it) {
        CP_WAIT0;
        sts_a(it);
        __syncthreads();
        if (it + 1 < NIT) {
            ldg_a(it + 1);
            ld_b(it + 1);
        }

        const uint32_t sbase = sb + (uint32_t)(it & 1) * STAGE;
        const uint32_t abase = sbase + a_off;
        const uint32_t bbase = sbase + b_off;

#pragma unroll
        for (int ks = 0; ks < 2; ++ks) {
            uint32_t af[2][4], bf[8][2];
            // A: 2 tiles of 16x16 (mf stride = 16 rows * 80B = 1280)
            ldsm_x4(af[0][0], af[0][1], af[0][2], af[0][3],
                    abase + ks * 32);
            ldsm_x4(af[1][0], af[1][1], af[1][2], af[1][3],
                    abase + 1280 + ks * 32);
            // B: 4 tiles of 16n x 16k (nf-pair stride = 1280)
#pragma unroll
            for (int nfp = 0; nfp < 4; ++nfp)
                ldsm_x4(bf[2 * nfp][0], bf[2 * nfp + 1][0],
                        bf[2 * nfp][1], bf[2 * nfp + 1][1],
                        bbase + nfp * 1280 + ks * 32);
#pragma unroll
            for (int mf = 0; mf < 2; ++mf)
#pragma unroll
                for (int nf = 0; nf < 8; ++nf)
                    mma_f16(acc[mf][nf], af[mf], bf[nf]);
        }
    }

    // ---- fused epilogue ----
    float uv[8][2], cv[8][2];
#pragma unroll
    for (int nf = 0; nf < 8; ++nf)
#pragma unroll
        for (int j = 0; j < 2; ++j) {
            int n = n0 + warp_n * 64 + nf * 8 + t * 2 + j;
            uv[nf][j] = u_w[n];
            cv[nf][j] = g_c[b_idx * ATT_ + n];
        }

    float part[2][2];
#pragma unroll
    for (int mf = 0; mf < 2; ++mf)
#pragma unroll
        for (int half = 0; half < 2; ++half) {
            float p = 0.f;
#pragma unroll
            for (int nf = 0; nf < 8; ++nf)
#pragma unroll
                for (int j = 0; j < 2; ++j) {
                    float z = acc[mf][nf][half * 2 + j] + cv[nf][j];
                    p += uv[nf][j] * tanh_hw(z);
                }
            part[mf][half] = p;
        }

#pragma unroll
    for (int mf = 0; mf < 2; ++mf)
#pragma unroll
        for (int half = 0; half < 2; ++half) {
            float p = part[mf][half];
            p += __shfl_xor_sync(0xffffffffu, p, 1);
            p += __shfl_xor_sync(0xffffffffu, p, 2);
            part[mf][half] = p;
        }

    __syncthreads();
    float* red = reinterpret_cast<float*>(smem);   // [128][2]
    if (t == 0) {
#pragma unroll
        for (int mf = 0; mf < 2; ++mf)
#pragma unroll
            for (int half = 0; half < 2; ++half) {
                int row = warp_m * 32 + mf * 16 + half * 8 + r;
                red[row * 2 + warp_n] = part[mf][half];
            }
    }
    __syncthreads();
    if (tid < BM)
        g_beta_part[blockIdx.x][m0 + tid] = red[tid * 2] + red[tid * 2 + 1];
}

// ---------------------------------------------------------------------------
// Fused softmax + weighted sum. grid (4 d-chunks, 64 b).
// ---------------------------------------------------------------------------
__global__ __launch_bounds__(256) void k_out(const int* __restrict__ h_mask,
                                             const float* __restrict__ h,
                                             float* __restrict__ out) {
    const int b = blockIdx.y;
    const int d0 = blockIdx.x * 256;
    const int tid = threadIdx.x;
    const int ds = tid & 63;
    const int ss = tid >> 6;

    __shared__ float salpha[S_];
    __shared__ float tmp[256];
    __shared__ float red[3][256];

    float beta[2];
#pragma unroll
    for (int k = 0; k < 2; ++k) {
        int s = tid + k * 256;
        int idx = b * S_ + s;
        float v = g_beta_part[0][idx] + g_beta_part[1][idx] +
                  g_beta_part[2][idx] + g_beta_part[3][idx];
        beta[k] = (h_mask[idx] != 0) ? v : -1e20f;
    }
    tmp[tid] = fmaxf(beta[0], beta[1]);
    __syncthreads();
#pragma unroll
    for (int off = 128; off; off >>= 1) {
        if (tid < off) tmp[tid] = fmaxf(tmp[tid], tmp[tid + off]);
        __syncthreads();
    }
    const float mx = tmp[0];
    __syncthreads();
    float e0 = __expf(beta[0] - mx);
    float e1 = __expf(beta[1] - mx);
    salpha[tid] = e0;
    salpha[tid + 256] = e1;
    tmp[tid] = e0 + e1;
    __syncthreads();
#pragma unroll
    for (int off = 128; off; off >>= 1) {
        if (tid < off) tmp[tid] += tmp[tid + off];
        __syncthreads();
    }
    const float inv = 1.0f / tmp[0];
    __syncthreads();

    float acc[4] = {0.f, 0.f, 0.f, 0.f};
    const float* hp = h + ((size_t)b * S_ + ss * 128) * H2_ + d0 + ds * 4;
    const float* al = salpha + ss * 128;
#pragma unroll 8
    for (int s = 0; s < 128; ++s) {
        float4 v = *reinterpret_cast<const float4*>(hp + (size_t)s * H2_);
        float a = al[s];
        acc[0] += a * v.x; acc[1] += a * v.y;
        acc[2] += a * v.z; acc[3] += a * v.w;
    }
    if (ss) {
#pragma unroll
        for (int k = 0; k < 4; ++k) red[ss - 1][ds * 4 + k] = acc[k];
    }
    __syncthreads();
    if (ss == 0) {
#pragma unroll
        for (int k = 0; k < 4; ++k) {
            float v = acc[k] + red[0][ds * 4 + k] + red[1][ds * 4 + k] +
                      red[2][ds * 4 + k];
            out[b * H2_ + d0 + ds * 4 + k] = v * inv;
        }
    }
}

// ---------------------------------------------------------------------------
extern "C" void kernel_launch(void* const* d_in, const int* in_sizes, int n_in,
                              void* d_out, int out_size) {
    const float* h      = (const float*)d_in[0];
    const int*   h_mask = (const int*)  d_in[1];
    const float* ht     = (const float*)d_in[2];
    const float* w1_w   = (const float*)d_in[3];
    const float* w1_b   = (const float*)d_in[4];
    const float* u_w    = (const float*)d_in[5];
    float* out = (float*)d_out;

    cudaFuncSetAttribute(k_gemm_beta,
                         cudaFuncAttributeMaxDynamicSharedMemorySize,
                         GEMM_SMEM);

    k_cvt_w<<<(ATT_ * H2_) / (256 * 8), 256>>>(w1_w);
    k_ht_mean<<<(B_ * H2_) / 256, 256>>>(ht);
    k_c<<<dim3(ATT_ / 8, B_ / 8), 256>>>(w1_w, w1_b);
    k_gemm_beta<<<dim3(ATT_ / BN, (B_ * S_) / BM), 256, GEMM_SMEM>>>(h, u_w);
    k_out<<<dim3(4, B_), 256>>>(h_mask, h, out);
}

// round 8
// speedup vs baseline: 1.4334x; 1.1016x over previous
#include <cuda_runtime.h>
#include <cuda_fp16.h>
#include <cstdint>

// Problem constants
#define B_    64
#define S_    512
#define T_    32
#define H2_   1024
#define ATT_  512
#define WSTR_ 2048

// GEMM tiling (fp16 mma.m16n8k16, fp32 accum)
#define BM 128
#define BN 128
#define BK 32
#define NIT (H2_ / BK)          // 32
#define RPW 20                  // uint32 per padded smem row (80 B)
#define ROWB 80
#define A_BYTES (BM * ROWB)     // 10240
#define B_BYTES (BN * ROWB)     // 10240
#define STAGE (A_BYTES + B_BYTES)          // 20480
#define GEMM_SMEM (2 * STAGE)              // 40960

// Scratch (device globals)
__device__ __half g_w16[ATT_ * H2_];              // fp16 copy of w1_w[:, :1024]
__device__ float  g_ht_mean[B_ * H2_];
__device__ float  g_c[B_ * ATT_];
__device__ float  g_beta_part[4][B_ * S_];

// ---------------------------------------------------------------------------
__device__ __forceinline__ void cp16(uint32_t smem_dst, const void* gsrc) {
    asm volatile("cp.async.cg.shared.global [%0], [%1], 16;\n"
                 :: "r"(smem_dst), "l"(gsrc));
}
#define CP_COMMIT asm volatile("cp.async.commit_group;\n" ::: "memory")
#define CP_WAIT0  asm volatile("cp.async.wait_group 0;\n" ::: "memory")

__device__ __forceinline__ uint32_t smem_u32(const void* p) {
    uint32_t a;
    asm("{ .reg .u64 t; cvta.to.shared.u64 t, %1; cvt.u32.u64 %0, t; }"
        : "=r"(a) : "l"(p));
    return a;
}

__device__ __forceinline__ void mma_f16(float* d, const uint32_t* a,
                                        const uint32_t* b) {
    asm volatile(
        "mma.sync.aligned.m16n8k16.row.col.f32.f16.f16.f32 "
        "{%0,%1,%2,%3}, {%4,%5,%6,%7}, {%8,%9}, {%0,%1,%2,%3};\n"
        : "+f"(d[0]), "+f"(d[1]), "+f"(d[2]), "+f"(d[3])
        : "r"(a[0]), "r"(a[1]), "r"(a[2]), "r"(a[3]), "r"(b[0]), "r"(b[1]));
}

__device__ __forceinline__ void ldsm_x4(uint32_t& r0, uint32_t& r1,
                                        uint32_t& r2, uint32_t& r3,
                                        uint32_t addr) {
    asm volatile(
        "ldmatrix.sync.aligned.m8n8.x4.shared.b16 {%0,%1,%2,%3}, [%4];"
        : "=r"(r0), "=r"(r1), "=r"(r2), "=r"(r3) : "r"(addr));
}

__device__ __forceinline__ float tanh_hw(float x) {
    float t;
    asm("tanh.approx.f32 %0, %1;" : "=f"(t) : "f"(x));
    return t;
}

// ---------------------------------------------------------------------------
__global__ void k_cvt_w(const float* __restrict__ w1_w) {
    size_t i = ((size_t)blockIdx.x * 256 + threadIdx.x) * 8;
    int row = (int)(i >> 10);
    int col = (int)(i & 1023);
    const float* src = w1_w + (size_t)row * WSTR_ + col;
    float4 f0 = *reinterpret_cast<const float4*>(src);
    float4 f1 = *reinterpret_cast<const float4*>(src + 4);
    __half2 a = __floats2half2_rn(f0.x, f0.y);
    __half2 b = __floats2half2_rn(f0.z, f0.w);
    __half2 c = __floats2half2_rn(f1.x, f1.y);
    __half2 d = __floats2half2_rn(f1.z, f1.w);
    uint4 v;
    v.x = *reinterpret_cast<uint32_t*>(&a);
    v.y = *reinterpret_cast<uint32_t*>(&b);
    v.z = *reinterpret_cast<uint32_t*>(&c);
    v.w = *reinterpret_cast<uint32_t*>(&d);
    *reinterpret_cast<uint4*>(&g_w16[i]) = v;
}

__global__ void k_ht_mean(const float* __restrict__ ht) {
    int idx = blockIdx.x * 256 + threadIdx.x;
    int b = idx >> 10;
    const float* p = ht + (size_t)b * T_ * H2_ + (idx & (H2_ - 1));
    float s = 0.f;
#pragma unroll
    for (int t = 0; t < T_; ++t) s += p[(size_t)t * H2_];
    g_ht_mean[idx] = s * (1.0f / T_);
}

// ---------------------------------------------------------------------------
// c[b,a] = dot(ht_mean[b], w1_w[a,1024:]) + bias[a]
// ---------------------------------------------------------------------------
__global__ __launch_bounds__(256) void k_c(const float* __restrict__ w1_w,
                                           const float* __restrict__ w1_b) {
    __shared__ float sw[8][H2_];   // 32 KB
    const int a0 = blockIdx.x * 8;
    const int b0 = blockIdx.y * 8;
    const int tid = threadIdx.x;
    for (int i = tid; i < 8 * 256; i += 256) {
        int row = i >> 8, c4 = i & 255;
        reinterpret_cast<float4*>(sw[row])[c4] =
            *reinterpret_cast<const float4*>(
                w1_w + (size_t)(a0 + row) * WSTR_ + H2_ + c4 * 4);
    }
    __syncthreads();
    const int wid = tid >> 5, lane = tid & 31;
    const float bias = w1_b[a0 + wid];
    const float4* swv = reinterpret_cast<const float4*>(sw[wid]);
#pragma unroll
    for (int bi = 0; bi < 8; ++bi) {
        int b = b0 + bi;
        const float4* hm =
            reinterpret_cast<const float4*>(g_ht_mean + b * H2_);
        float s = 0.f;
#pragma unroll
        for (int q = 0; q < 8; ++q) {
            float4 hv = hm[lane + q * 32];
            float4 wv = swv[lane + q * 32];
            s += hv.x * wv.x + hv.y * wv.y + hv.z * wv.z + hv.w * wv.w;
        }
#pragma unroll
        for (int off = 16; off; off >>= 1)
            s += __shfl_down_sync(0xffffffffu, s, off);
        if (lane == 0) g_c[b * ATT_ + a0 + wid] = s + bias;
    }
}

// ---------------------------------------------------------------------------
// Main fused GEMM (fp16 HMMA, fp32 accum), 128x128 CTA tile, 128 threads,
// 4 warps with 64x64 warp tiles, 2 CTAs/SM, ldmatrix fragment loads.
// ---------------------------------------------------------------------------
__global__ __launch_bounds__(128, 2) void k_gemm_beta(
    const float* __restrict__ h,
    const float* __restrict__ u_w)
{
    extern __shared__ char smem[];
    const uint32_t sb = smem_u32(smem);

    const int tid = threadIdx.x;
    const int lane = tid & 31;
    const int wid = tid >> 5;
    const int warp_m = wid >> 1;      // 0..1, 64 rows
    const int warp_n = wid & 1;       // 0..1, 64 cols
    const int r = lane >> 2;          // 0..7
    const int t = lane & 3;           // 0..3

    const int n0 = blockIdx.x * BN;
    const int m0 = blockIdx.y * BM;
    const int b_idx = m0 >> 9;

    // ldmatrix per-lane base offsets (bytes)
    const int lane7 = lane & 7;
    const int lg8 = (lane >> 3) & 1;
    const int lg16 = lane >> 4;
    const uint32_t a_off =
        (uint32_t)((warp_m * 64 + lg8 * 8 + lane7) * ROWB + lg16 * 16);
    const uint32_t b_off =
        (uint32_t)(A_BYTES + (warp_n * 64 + lg8 * 8 + lane7) * ROWB +
                   lg16 * 16);

    // A staging: 8 lanes per row (coalesced). Thread covers rows
    // s*16 + (tid>>3), 16B fp32 chunk q = tid&7 (k offsets q*4..q*4+3).
    const int row_base = tid >> 3;
    const int q8 = tid & 7;
    const float* aptr = h + (size_t)(m0 + row_base) * H2_ + q8 * 4;
    const uint32_t asmem = (uint32_t)(row_base * ROWB + q8 * 8);

    float acc[4][8][4];
#pragma unroll
    for (int i = 0; i < 4; ++i)
#pragma unroll
        for (int j = 0; j < 8; ++j)
#pragma unroll
            for (int k = 0; k < 4; ++k) acc[i][j][k] = 0.f;

    float4 areg[8];
    auto ldg_a = [&](int it) {
        const float* p = aptr + it * BK;
#pragma unroll
        for (int s = 0; s < 8; ++s)
            areg[s] = *reinterpret_cast<const float4*>(
                p + (size_t)s * 16 * H2_);
    };
    auto sts_a = [&](int it) {
        const uint32_t dst0 = sb + (uint32_t)(it & 1) * STAGE + asmem;
#pragma unroll
        for (int s = 0; s < 8; ++s) {
            __half2 lo = __floats2half2_rn(areg[s].x, areg[s].y);
            __half2 hi = __floats2half2_rn(areg[s].z, areg[s].w);
            uint32_t u0 = *reinterpret_cast<uint32_t*>(&lo);
            uint32_t u1 = *reinterpret_cast<uint32_t*>(&hi);
            asm volatile("st.shared.v2.b32 [%0], {%1,%2};"
                         :: "r"(dst0 + (uint32_t)(s * 16 * ROWB)),
                            "r"(u0), "r"(u1));
        }
    };
    auto ld_b = [&](int it) {
        const uint32_t base = sb + (uint32_t)(it & 1) * STAGE + A_BYTES;
        const int kb = it * BK;
#pragma unroll
        for (int s = 0; s < 4; ++s) {
            int id = tid + s * 128;
            int row = id >> 2, q = id & 3;
            cp16(base + (uint32_t)(row * ROWB + q * 16),
                 g_w16 + (size_t)(n0 + row) * H2_ + kb + q * 8);
        }
        CP_COMMIT;
    };

    ldg_a(0);
    ld_b(0);

    for (int it = 0; it < NIT; ++it) {
        CP_WAIT0;
        sts_a(it);
        __syncthreads();
        if (it + 1 < NIT) {
            ldg_a(it + 1);
            ld_b(it + 1);
        }

        const uint32_t sbase = sb + (uint32_t)(it & 1) * STAGE;
        const uint32_t abase = sbase + a_off;
        const uint32_t bbase = sbase + b_off;

#pragma unroll
        for (int ks = 0; ks < 2; ++ks) {
            uint32_t af[4][4], bf[8][2];
            // A: 4 tiles of 16x16 (mf stride = 16 rows * 80B = 1280)
#pragma unroll
            for (int mf = 0; mf < 4; ++mf)
                ldsm_x4(af[mf][0], af[mf][1], af[mf][2], af[mf][3],
                        abase + mf * 1280 + ks * 32);
            // B: 4 ldsm.x4 -> 8 n8k16 tiles (nf-pair stride = 1280)
#pragma unroll
            for (int nfp = 0; nfp < 4; ++nfp)
                ldsm_x4(bf[2 * nfp][0], bf[2 * nfp + 1][0],
                        bf[2 * nfp][1], bf[2 * nfp + 1][1],
                        bbase + nfp * 1280 + ks * 32);
#pragma unroll
            for (int mf = 0; mf < 4; ++mf)
#pragma unroll
                for (int nf = 0; nf < 8; ++nf)
                    mma_f16(acc[mf][nf], af[mf], bf[nf]);
        }
    }

    // ---- fused epilogue ----
    float uv[8][2], cv[8][2];
#pragma unroll
    for (int nf = 0; nf < 8; ++nf)
#pragma unroll
        for (int j = 0; j < 2; ++j) {
            int n = n0 + warp_n * 64 + nf * 8 + t * 2 + j;
            uv[nf][j] = u_w[n];
            cv[nf][j] = g_c[b_idx * ATT_ + n];
        }

    float part[4][2];
#pragma unroll
    for (int mf = 0; mf < 4; ++mf)
#pragma unroll
        for (int half = 0; half < 2; ++half) {
            float p = 0.f;
#pragma unroll
            for (int nf = 0; nf < 8; ++nf)
#pragma unroll
                for (int j = 0; j < 2; ++j) {
                    float z = acc[mf][nf][half * 2 + j] + cv[nf][j];
                    p += uv[nf][j] * tanh_hw(z);
                }
            part[mf][half] = p;
        }

#pragma unroll
    for (int mf = 0; mf < 4; ++mf)
#pragma unroll
        for (int half = 0; half < 2; ++half) {
            float p = part[mf][half];
            p += __shfl_xor_sync(0xffffffffu, p, 1);
            p += __shfl_xor_sync(0xffffffffu, p, 2);
            part[mf][half] = p;
        }

    __syncthreads();
    float* red = reinterpret_cast<float*>(smem);   // [128][2]
    if (t == 0) {
#pragma unroll
        for (int mf = 0; mf < 4; ++mf)
#pragma unroll
            for (int half = 0; half < 2; ++half) {
                int row = warp_m * 64 + mf * 16 + half * 8 + r;
                red[row * 2 + warp_n] = part[mf][half];
            }
    }
    __syncthreads();
    if (tid < BM)
        g_beta_part[blockIdx.x][m0 + tid] = red[tid * 2] + red[tid * 2 + 1];
}

// ---------------------------------------------------------------------------
// Fused softmax + weighted sum. grid (4 d-chunks, 64 b).
// ---------------------------------------------------------------------------
__global__ __launch_bounds__(256) void k_out(const int* __restrict__ h_mask,
                                             const float* __restrict__ h,
                                             float* __restrict__ out) {
    const int b = blockIdx.y;
    const int d0 = blockIdx.x * 256;
    const int tid = threadIdx.x;
    const int ds = tid & 63;
    const int ss = tid >> 6;

    __shared__ float salpha[S_];
    __shared__ float tmp[256];
    __shared__ float red[3][256];

    float beta[2];
#pragma unroll
    for (int k = 0; k < 2; ++k) {
        int s = tid + k * 256;
        int idx = b * S_ + s;
        float v = g_beta_part[0][idx] + g_beta_part[1][idx] +
                  g_beta_part[2][idx] + g_beta_part[3][idx];
        beta[k] = (h_mask[idx] != 0) ? v : -1e20f;
    }
    tmp[tid] = fmaxf(beta[0], beta[1]);
    __syncthreads();
#pragma unroll
    for (int off = 128; off; off >>= 1) {
        if (tid < off) tmp[tid] = fmaxf(tmp[tid], tmp[tid + off]);
        __syncthreads();
    }
    const float mx = tmp[0];
    __syncthreads();
    float e0 = __expf(beta[0] - mx);
    float e1 = __expf(beta[1] - mx);
    salpha[tid] = e0;
    salpha[tid + 256] = e1;
    tmp[tid] = e0 + e1;
    __syncthreads();
#pragma unroll
    for (int off = 128; off; off >>= 1) {
        if (tid < off) tmp[tid] += tmp[tid + off];
        __syncthreads();
    }
    const float inv = 1.0f / tmp[0];
    __syncthreads();

    float acc[4] = {0.f, 0.f, 0.f, 0.f};
    const float* hp = h + ((size_t)b * S_ + ss * 128) * H2_ + d0 + ds * 4;
    const float* al = salpha + ss * 128;
#pragma unroll 8
    for (int s = 0; s < 128; ++s) {
        float4 v = *reinterpret_cast<const float4*>(hp + (size_t)s * H2_);
        float a = al[s];
        acc[0] += a * v.x; acc[1] += a * v.y;
        acc[2] += a * v.z; acc[3] += a * v.w;
    }
    if (ss) {
#pragma unroll
        for (int k = 0; k < 4; ++k) red[ss - 1][ds * 4 + k] = acc[k];
    }
    __syncthreads();
    if (ss == 0) {
#pragma unroll
        for (int k = 0; k < 4; ++k) {
            float v = acc[k] + red[0][ds * 4 + k] + red[1][ds * 4 + k] +
                      red[2][ds * 4 + k];
            out[b * H2_ + d0 + ds * 4 + k] = v * inv;
        }
    }
}

// ---------------------------------------------------------------------------
extern "C" void kernel_launch(void* const* d_in, const int* in_sizes, int n_in,
                              void* d_out, int out_size) {
    const float* h      = (const float*)d_in[0];
    const int*   h_mask = (const int*)  d_in[1];
    const float* ht     = (const float*)d_in[2];
    const float* w1_w   = (const float*)d_in[3];
    const float* w1_b   = (const float*)d_in[4];
    const float* u_w    = (const float*)d_in[5];
    float* out = (float*)d_out;

    cudaFuncSetAttribute(k_gemm_beta,
                         cudaFuncAttributeMaxDynamicSharedMemorySize,
                         GEMM_SMEM);

    k_cvt_w<<<(ATT_ * H2_) / (256 * 8), 256>>>(w1_w);
    k_ht_mean<<<(B_ * H2_) / 256, 256>>>(ht);
    k_c<<<dim3(ATT_ / 8, B_ / 8), 256>>>(w1_w, w1_b);
    k_gemm_beta<<<dim3(ATT_ / BN, (B_ * S_) / BM), 128, GEMM_SMEM>>>(h, u_w);
    k_out<<<dim3(4, B_), 256>>>(h_mask, h, out);
}

// round 9
// speedup vs baseline: 1.5300x; 1.0674x over previous
#include <cuda_runtime.h>
#include <cuda_fp16.h>
#include <cstdint>

// Problem constants
#define B_    64
#define S_    512
#define T_    32
#define H2_   1024
#define ATT_  512
#define WSTR_ 2048

// GEMM tiling (fp16 mma.m16n8k16, fp32 accum)
#define BM 128
#define BN 128
#define BK 32
#define NIT (H2_ / BK)          // 32
#define ROWB 80                 // padded smem row bytes (conflict-free ldmatrix)
#define A_BYTES (BM * ROWB)     // 10240
#define B_BYTES (BN * ROWB)     // 10240
#define STAGE (A_BYTES + B_BYTES)          // 20480
#define NSTAGE 4
#define GEMM_SMEM (NSTAGE * STAGE)         // 81920

// Scratch (device globals)
__device__ __half g_w16[ATT_ * H2_];              // fp16 copy of w1_w[:, :1024]
__device__ float  g_ht_mean[B_ * H2_];
__device__ float  g_c[B_ * ATT_];
__device__ float  g_beta_part[4][B_ * S_];

// ---------------------------------------------------------------------------
__device__ __forceinline__ void cp16(uint32_t smem_dst, const void* gsrc) {
    asm volatile("cp.async.cg.shared.global [%0], [%1], 16;\n"
                 :: "r"(smem_dst), "l"(gsrc));
}
#define CP_COMMIT asm volatile("cp.async.commit_group;\n" ::: "memory")
#define CP_WAIT2  asm volatile("cp.async.wait_group 2;\n" ::: "memory")

__device__ __forceinline__ uint32_t smem_u32(const void* p) {
    uint32_t a;
    asm("{ .reg .u64 t; cvta.to.shared.u64 t, %1; cvt.u32.u64 %0, t; }"
        : "=r"(a) : "l"(p));
    return a;
}

__device__ __forceinline__ void mma_f16(float* d, const uint32_t* a,
                                        const uint32_t* b) {
    asm volatile(
        "mma.sync.aligned.m16n8k16.row.col.f32.f16.f16.f32 "
        "{%0,%1,%2,%3}, {%4,%5,%6,%7}, {%8,%9}, {%0,%1,%2,%3};\n"
        : "+f"(d[0]), "+f"(d[1]), "+f"(d[2]), "+f"(d[3])
        : "r"(a[0]), "r"(a[1]), "r"(a[2]), "r"(a[3]), "r"(b[0]), "r"(b[1]));
}

__device__ __forceinline__ void ldsm_x4(uint32_t& r0, uint32_t& r1,
                                        uint32_t& r2, uint32_t& r3,
                                        uint32_t addr) {
    asm volatile(
        "ldmatrix.sync.aligned.m8n8.x4.shared.b16 {%0,%1,%2,%3}, [%4];"
        : "=r"(r0), "=r"(r1), "=r"(r2), "=r"(r3) : "r"(addr));
}

__device__ __forceinline__ float tanh_hw(float x) {
    float t;
    asm("tanh.approx.f32 %0, %1;" : "=f"(t) : "f"(x));
    return t;
}

// ---------------------------------------------------------------------------
__global__ void k_cvt_w(const float* __restrict__ w1_w) {
    size_t i = ((size_t)blockIdx.x * 256 + threadIdx.x) * 8;
    int row = (int)(i >> 10);
    int col = (int)(i & 1023);
    const float* src = w1_w + (size_t)row * WSTR_ + col;
    float4 f0 = *reinterpret_cast<const float4*>(src);
    float4 f1 = *reinterpret_cast<const float4*>(src + 4);
    __half2 a = __floats2half2_rn(f0.x, f0.y);
    __half2 b = __floats2half2_rn(f0.z, f0.w);
    __half2 c = __floats2half2_rn(f1.x, f1.y);
    __half2 d = __floats2half2_rn(f1.z, f1.w);
    uint4 v;
    v.x = *reinterpret_cast<uint32_t*>(&a);
    v.y = *reinterpret_cast<uint32_t*>(&b);
    v.z = *reinterpret_cast<uint32_t*>(&c);
    v.w = *reinterpret_cast<uint32_t*>(&d);
    *reinterpret_cast<uint4*>(&g_w16[i]) = v;
}

__global__ void k_ht_mean(const float* __restrict__ ht) {
    int idx = blockIdx.x * 256 + threadIdx.x;
    int b = idx >> 10;
    const float* p = ht + (size_t)b * T_ * H2_ + (idx & (H2_ - 1));
    float s = 0.f;
#pragma unroll
    for (int t = 0; t < T_; ++t) s += p[(size_t)t * H2_];
    g_ht_mean[idx] = s * (1.0f / T_);
}

// ---------------------------------------------------------------------------
// c[b,a] = dot(ht_mean[b], w1_w[a,1024:]) + bias[a]
// ---------------------------------------------------------------------------
__global__ __launch_bounds__(256) void k_c(const float* __restrict__ w1_w,
                                           const float* __restrict__ w1_b) {
    __shared__ float sw[8][H2_];   // 32 KB
    const int a0 = blockIdx.x * 8;
    const int b0 = blockIdx.y * 8;
    const int tid = threadIdx.x;
    for (int i = tid; i < 8 * 256; i += 256) {
        int row = i >> 8, c4 = i & 255;
        reinterpret_cast<float4*>(sw[row])[c4] =
            *reinterpret_cast<const float4*>(
                w1_w + (size_t)(a0 + row) * WSTR_ + H2_ + c4 * 4);
    }
    __syncthreads();
    const int wid = tid >> 5, lane = tid & 31;
    const float bias = w1_b[a0 + wid];
    const float4* swv = reinterpret_cast<const float4*>(sw[wid]);
#pragma unroll
    for (int bi = 0; bi < 8; ++bi) {
        int b = b0 + bi;
        const float4* hm =
            reinterpret_cast<const float4*>(g_ht_mean + b * H2_);
        float s = 0.f;
#pragma unroll
        for (int q = 0; q < 8; ++q) {
            float4 hv = hm[lane + q * 32];
            float4 wv = swv[lane + q * 32];
            s += hv.x * wv.x + hv.y * wv.y + hv.z * wv.z + hv.w * wv.w;
        }
#pragma unroll
        for (int off = 16; off; off >>= 1)
            s += __shfl_down_sync(0xffffffffu, s, off);
        if (lane == 0) g_c[b * ATT_ + a0 + wid] = s + bias;
    }
}

// ---------------------------------------------------------------------------
// Main fused GEMM (fp16 HMMA, fp32 accum), 128x128 CTA tile, 128 threads,
// 4 warps with 64x64 warp tiles, 2 CTAs/SM, 4-stage pipeline.
//   stage it:   consumed by MMA at iter it
//   STS-A writes stage it+2 (data LDG'd at iter it-1)
//   cp.async-B targets stage it+3; wait_group 2 at loop head
// ---------------------------------------------------------------------------
__global__ __launch_bounds__(128, 2) void k_gemm_beta(
    const float* __restrict__ h,
    const float* __restrict__ u_w)
{
    extern __shared__ char smem[];
    const uint32_t sb = smem_u32(smem);

    const int tid = threadIdx.x;
    const int lane = tid & 31;
    const int wid = tid >> 5;
    const int warp_m = wid >> 1;      // 0..1, 64 rows
    const int warp_n = wid & 1;       // 0..1, 64 cols
    const int r = lane >> 2;          // 0..7
    const int t = lane & 3;           // 0..3

    const int n0 = blockIdx.x * BN;
    const int m0 = blockIdx.y * BM;
    const int b_idx = m0 >> 9;

    // ldmatrix per-lane base offsets (bytes)
    const int lane7 = lane & 7;
    const int lg8 = (lane >> 3) & 1;
    const int lg16 = lane >> 4;
    const uint32_t a_off =
        (uint32_t)((warp_m * 64 + lg8 * 8 + lane7) * ROWB + lg16 * 16);
    const uint32_t b_off =
        (uint32_t)(A_BYTES + (warp_n * 64 + lg8 * 8 + lane7) * ROWB +
                   lg16 * 16);

    // A staging: 8 lanes per row (coalesced LDG.128). Thread covers rows
    // s*16 + (tid>>3), fp32 chunk q = tid&7.
    const int row_base = tid >> 3;
    const int q8 = tid & 7;
    const float* aptr = h + (size_t)(m0 + row_base) * H2_ + q8 * 4;
    const uint32_t asmem = (uint32_t)(row_base * ROWB + q8 * 8);

    float acc[4][8][4];
#pragma unroll
    for (int i = 0; i < 4; ++i)
#pragma unroll
        for (int j = 0; j < 8; ++j)
#pragma unroll
            for (int k = 0; k < 4; ++k) acc[i][j][k] = 0.f;

    float4 areg[8];
    auto ldg_a = [&](int it) {
        const float* p = aptr + it * BK;
#pragma unroll
        for (int s = 0; s < 8; ++s)
            areg[s] = *reinterpret_cast<const float4*>(
                p + (size_t)s * 16 * H2_);
    };
    auto sts_a = [&](int it) {
        const uint32_t dst0 = sb + (uint32_t)((it & 3) * STAGE) + asmem;
#pragma unroll
        for (int s = 0; s < 8; ++s) {
            __half2 lo = __floats2half2_rn(areg[s].x, areg[s].y);
            __half2 hi = __floats2half2_rn(areg[s].z, areg[s].w);
            uint32_t u0 = *reinterpret_cast<uint32_t*>(&lo);
            uint32_t u1 = *reinterpret_cast<uint32_t*>(&hi);
            asm volatile("st.shared.v2.b32 [%0], {%1,%2};"
                         :: "r"(dst0 + (uint32_t)(s * 16 * ROWB)),
                            "r"(u0), "r"(u1));
        }
    };
    auto ld_b = [&](int it) {           // one commit group per call
        const uint32_t base = sb + (uint32_t)((it & 3) * STAGE) + A_BYTES;
        const int kb = it * BK;
#pragma unroll
        for (int s = 0; s < 4; ++s) {
            int id = tid + s * 128;
            int row = id >> 2, q = id & 3;
            cp16(base + (uint32_t)(row * ROWB + q * 16),
                 g_w16 + (size_t)(n0 + row) * H2_ + kb + q * 8);
        }
        CP_COMMIT;
    };

    // ---- prologue: A stages 0,1 stored; areg holds stage 2; B groups 0,1,2
    ldg_a(0); sts_a(0);
    ldg_a(1); sts_a(1);
    ldg_a(2);
    ld_b(0); ld_b(1); ld_b(2);

    for (int it = 0; it < NIT; ++it) {
        CP_WAIT2;                 // stage it's B landed (2 younger groups ok)
        __syncthreads();          // stage it's A (STS 2 iters ago) visible

        const uint32_t sbase = sb + (uint32_t)((it & 3) * STAGE);
        const uint32_t abase = sbase + a_off;
        const uint32_t bbase = sbase + b_off;

#pragma unroll
        for (int ks = 0; ks < 2; ++ks) {
            uint32_t af[4][4], bf[8][2];
#pragma unroll
            for (int mf = 0; mf < 4; ++mf)
                ldsm_x4(af[mf][0], af[mf][1], af[mf][2], af[mf][3],
                        abase + mf * 1280 + ks * 32);
#pragma unroll
            for (int nfp = 0; nfp < 4; ++nfp)
                ldsm_x4(bf[2 * nfp][0], bf[2 * nfp + 1][0],
                        bf[2 * nfp][1], bf[2 * nfp + 1][1],
                        bbase + nfp * 1280 + ks * 32);
#pragma unroll
            for (int mf = 0; mf < 4; ++mf)
#pragma unroll
                for (int nf = 0; nf < 8; ++nf)
                    mma_f16(acc[mf][nf], af[mf], bf[nf]);
        }

        // staging for future stages (off the critical path)
        if (it + 2 < NIT) sts_a(it + 2);        // uses areg (ldg'd last iter)
        if (it + 3 < NIT) {
            ldg_a(it + 3);                      // refill areg
            ld_b(it + 3);                       // commits one group
        } else {
            CP_COMMIT;                          // empty group keeps count
        }
    }

    // ---- fused epilogue ----
    float uv[8][2], cv[8][2];
#pragma unroll
    for (int nf = 0; nf < 8; ++nf)
#pragma unroll
        for (int j = 0; j < 2; ++j) {
            int n = n0 + warp_n * 64 + nf * 8 + t * 2 + j;
            uv[nf][j] = u_w[n];
            cv[nf][j] = g_c[b_idx * ATT_ + n];
        }

    float part[4][2];
#pragma unroll
    for (int mf = 0; mf < 4; ++mf)
#pragma unroll
        for (int half = 0; half < 2; ++half) {
            float p = 0.f;
#pragma unroll
            for (int nf = 0; nf < 8; ++nf)
#pragma unroll
                for (int j = 0; j < 2; ++j) {
                    float z = acc[mf][nf][half * 2 + j] + cv[nf][j];
                    p += uv[nf][j] * tanh_hw(z);
                }
            part[mf][half] = p;
        }

#pragma unroll
    for (int mf = 0; mf < 4; ++mf)
#pragma unroll
        for (int half = 0; half < 2; ++half) {
            float p = part[mf][half];
            p += __shfl_xor_sync(0xffffffffu, p, 1);
            p += __shfl_xor_sync(0xffffffffu, p, 2);
            part[mf][half] = p;
        }

    __syncthreads();
    float* red = reinterpret_cast<float*>(smem);   // [128][2]
    if (t == 0) {
#pragma unroll
        for (int mf = 0; mf < 4; ++mf)
#pragma unroll
            for (int half = 0; half < 2; ++half) {
                int row = warp_m * 64 + mf * 16 + half * 8 + r;
                red[row * 2 + warp_n] = part[mf][half];
            }
    }
    __syncthreads();
    if (tid < BM)
        g_beta_part[blockIdx.x][m0 + tid] = red[tid * 2] + red[tid * 2 + 1];
}

// ---------------------------------------------------------------------------
// Fused softmax + weighted sum. grid (4 d-chunks, 64 b).
// ---------------------------------------------------------------------------
__global__ __launch_bounds__(256) void k_out(const int* __restrict__ h_mask,
                                             const float* __restrict__ h,
                                             float* __restrict__ out) {
    const int b = blockIdx.y;
    const int d0 = blockIdx.x * 256;
    const int tid = threadIdx.x;
    const int ds = tid & 63;
    const int ss = tid >> 6;

    __shared__ float salpha[S_];
    __shared__ float tmp[256];
    __shared__ float red[3][256];

    float beta[2];
#pragma unroll
    for (int k = 0; k < 2; ++k) {
        int s = tid + k * 256;
        int idx = b * S_ + s;
        float v = g_beta_part[0][idx] + g_beta_part[1][idx] +
                  g_beta_part[2][idx] + g_beta_part[3][idx];
        beta[k] = (h_mask[idx] != 0) ? v : -1e20f;
    }
    tmp[tid] = fmaxf(beta[0], beta[1]);
    __syncthreads();
#pragma unroll
    for (int off = 128; off; off >>= 1) {
        if (tid < off) tmp[tid] = fmaxf(tmp[tid], tmp[tid + off]);
        __syncthreads();
    }
    const float mx = tmp[0];
    __syncthreads();
    float e0 = __expf(beta[0] - mx);
    float e1 = __expf(beta[1] - mx);
    salpha[tid] = e0;
    salpha[tid + 256] = e1;
    tmp[tid] = e0 + e1;
    __syncthreads();
#pragma unroll
    for (int off = 128; off; off >>= 1) {
        if (tid < off) tmp[tid] += tmp[tid + off];
        __syncthreads();
    }
    const float inv = 1.0f / tmp[0];
    __syncthreads();

    float acc[4] = {0.f, 0.f, 0.f, 0.f};
    const float* hp = h + ((size_t)b * S_ + ss * 128) * H2_ + d0 + ds * 4;
    const float* al = salpha + ss * 128;
#pragma unroll 8
    for (int s = 0; s < 128; ++s) {
        float4 v = *reinterpret_cast<const float4*>(hp + (size_t)s * H2_);
        float a = al[s];
        acc[0] += a * v.x; acc[1] += a * v.y;
        acc[2] += a * v.z; acc[3] += a * v.w;
    }
    if (ss) {
#pragma unroll
        for (int k = 0; k < 4; ++k) red[ss - 1][ds * 4 + k] = acc[k];
    }
    __syncthreads();
    if (ss == 0) {
#pragma unroll
        for (int k = 0; k < 4; ++k) {
            float v = acc[k] + red[0][ds * 4 + k] + red[1][ds * 4 + k] +
                      red[2][ds * 4 + k];
            out[b * H2_ + d0 + ds * 4 + k] = v * inv;
        }
    }
}

// ---------------------------------------------------------------------------
extern "C" void kernel_launch(void* const* d_in, const int* in_sizes, int n_in,
                              void* d_out, int out_size) {
    const float* h      = (const float*)d_in[0];
    const int*   h_mask = (const int*)  d_in[1];
    const float* ht     = (const float*)d_in[2];
    const float* w1_w   = (const float*)d_in[3];
    const float* w1_b   = (const float*)d_in[4];
    const float* u_w    = (const float*)d_in[5];
    float* out = (float*)d_out;

    cudaFuncSetAttribute(k_gemm_beta,
                         cudaFuncAttributeMaxDynamicSharedMemorySize,
                         GEMM_SMEM);

    k_cvt_w<<<(ATT_ * H2_) / (256 * 8), 256>>>(w1_w);
    k_ht_mean<<<(B_ * H2_) / 256, 256>>>(ht);
    k_c<<<dim3(ATT_ / 8, B_ / 8), 256>>>(w1_w, w1_b);
    k_gemm_beta<<<dim3(ATT_ / BN, (B_ * S_) / BM), 128, GEMM_SMEM>>>(h, u_w);
    k_out<<<dim3(4, B_), 256>>>(h_mask, h, out);
}